// round 12
// baseline (speedup 1.0000x reference)
#include <cuda_runtime.h>

#define DOUT 128
#define EDIM 16
#define MAX_NODES 100000
#define CAP 64
#define FULL 0xffffffffu

typedef unsigned long long u64;

// Scratch (device globals — no allocations allowed)
__device__ float g_xw[(size_t)MAX_NODES * DOUT];   // 51.2 MB, kept L2-resident
__device__ int   g_cnt[MAX_NODES];
__device__ int2  g_elist[(size_t)MAX_NODES * CAP]; // (src, edge_id) buckets

// Packed fp32x2 ops (ptxas never auto-emits these from C++).
__device__ __forceinline__ u64 ffma2(u64 a, u64 b, u64 c) {
    u64 d;
    asm("fma.rn.f32x2 %0, %1, %2, %3;" : "=l"(d) : "l"(a), "l"(b), "l"(c));
    return d;
}
__device__ __forceinline__ u64 fadd2(u64 a, u64 b) {
    u64 d;
    asm("add.rn.f32x2 %0, %1, %2;" : "=l"(d) : "l"(a), "l"(b));
    return d;
}
__device__ __forceinline__ u64 splat2(float v) {
    u64 d;
    asm("mov.b64 %0, {%1, %1};" : "=l"(d) : "f"(v));
    return d;
}

// L2 eviction policies via createpolicy + cache_hint (width-agnostic form).
__device__ __forceinline__ u64 policy_evict_last() {
    u64 p;
    asm("createpolicy.fractional.L2::evict_last.b64 %0, 1.0;" : "=l"(p));
    return p;
}
__device__ __forceinline__ u64 policy_evict_first() {
    u64 p;
    asm("createpolicy.fractional.L2::evict_first.b64 %0, 1.0;" : "=l"(p));
    return p;
}
// xw gather: one u64 (this lane's 2 cols), keep in L2.
__device__ __forceinline__ u64 ldg_xw(const float* p, u64 pol) {
    u64 v;
    asm volatile("ld.global.nc.L2::cache_hint.b64 %0, [%1], %2;"
                 : "=l"(v) : "l"(p), "l"(pol));
    return v;
}
// ea row load: streaming.
__device__ __forceinline__ float4 ldg_ea(const float4* p, u64 pol) {
    float4 v;
    asm volatile("ld.global.nc.L2::cache_hint.v4.f32 {%0, %1, %2, %3}, [%4], %5;"
                 : "=f"(v.x), "=f"(v.y), "=f"(v.z), "=f"(v.w) : "l"(p), "l"(pol));
    return v;
}
__device__ __forceinline__ void st_out(float* p, u64 pol, u64 v) {
    asm volatile("st.global.L2::cache_hint.b64 [%0], %1, %2;"
                 :: "l"(p), "l"(v), "l"(pol));
}
__device__ __forceinline__ void pf_l2(const void* p) {
    asm volatile("prefetch.global.L2 [%0];" :: "l"(p));
}

__global__ void zero_cnt_kernel(int n) {
    int i = blockIdx.x * blockDim.x + threadIdx.x;
    if (i < n) g_cnt[i] = 0;
}

// xw = x @ W. 64 rows/block, 256 threads, thread = 8 rows x 4 cols, f32x2 math.
__global__ __launch_bounds__(256)
void gemm_xw_kernel(const float* __restrict__ x, const float* __restrict__ W, int n) {
    __shared__ float Ws[DOUT][DOUT];
    __shared__ float xs[64][DOUT];
    int tid = threadIdx.x;

    const float4* W4 = (const float4*)W;
    float4* Ws4 = (float4*)Ws;
    #pragma unroll
    for (int i = 0; i < 16; i++) Ws4[tid + i * 256] = W4[tid + i * 256];

    int row0 = blockIdx.x * 64;
    const float4* x4 = (const float4*)(x + (size_t)row0 * DOUT);
    float4* xs4 = (float4*)xs;
    #pragma unroll
    for (int i = 0; i < 8; i++) {
        int idx = tid + i * 256;
        int grow = row0 + (idx >> 5);
        if (grow < n) xs4[idx] = x4[idx];
    }
    __syncthreads();

    int rg = tid >> 5;
    int cg = tid & 31;

    u64 acc[8][2];
    #pragma unroll
    for (int r = 0; r < 8; r++) { acc[r][0] = 0ULL; acc[r][1] = 0ULL; }

    #pragma unroll 4
    for (int k = 0; k < DOUT; k += 2) {
        const u64* wa = (const u64*)&Ws[k][cg * 4];
        const u64* wb = (const u64*)&Ws[k + 1][cg * 4];
        u64 wa0 = wa[0], wa1 = wa[1];
        u64 wb0 = wb[0], wb1 = wb[1];
        #pragma unroll
        for (int r = 0; r < 8; r++) {
            float2 xp = *(const float2*)&xs[rg * 8 + r][k];
            u64 xk0 = splat2(xp.x);
            u64 xk1 = splat2(xp.y);
            acc[r][0] = ffma2(xk0, wa0, acc[r][0]);
            acc[r][1] = ffma2(xk0, wa1, acc[r][1]);
            acc[r][0] = ffma2(xk1, wb0, acc[r][0]);
            acc[r][1] = ffma2(xk1, wb1, acc[r][1]);
        }
    }

    #pragma unroll
    for (int r = 0; r < 8; r++) {
        int grow = row0 + rg * 8 + r;
        if (grow < n) {
            u64* dst = (u64*)&g_xw[(size_t)grow * DOUT + cg * 4];
            dst[0] = acc[r][0];
            dst[1] = acc[r][1];
        }
    }
}

// One thread per edge: append (src, e) to dst's bucket. Int atomics only.
__global__ __launch_bounds__(256)
void scatter_kernel(const int* __restrict__ ei, int nE) {
    int e = blockIdx.x * blockDim.x + threadIdx.x;
    if (e >= nE) return;
    int src = ei[e];
    int dst = ei[nE + e];
    int slot = atomicAdd(&g_cnt[dst], 1);
    if (slot < CAP)
        g_elist[(size_t)dst * CAP + slot] = make_int2(src, e);
}

// Modulate one ea row against the 2-col weight slice (two chains of 8).
__device__ __forceinline__ u64 modulate2(float4 A0, float4 A1, float4 A2, float4 A3,
                                         const u64 wp[EDIM]) {
    u64 c0 = 0, c1 = 0;
    c0 = ffma2(splat2(A0.x), wp[0],  c0);  c1 = ffma2(splat2(A0.y), wp[1],  c1);
    c0 = ffma2(splat2(A0.z), wp[2],  c0);  c1 = ffma2(splat2(A0.w), wp[3],  c1);
    c0 = ffma2(splat2(A1.x), wp[4],  c0);  c1 = ffma2(splat2(A1.y), wp[5],  c1);
    c0 = ffma2(splat2(A1.z), wp[6],  c0);  c1 = ffma2(splat2(A1.w), wp[7],  c1);
    c0 = ffma2(splat2(A2.x), wp[8],  c0);  c1 = ffma2(splat2(A2.y), wp[9],  c1);
    c0 = ffma2(splat2(A2.z), wp[10], c0);  c1 = ffma2(splat2(A2.w), wp[11], c1);
    c0 = ffma2(splat2(A3.x), wp[12], c0);  c1 = ffma2(splat2(A3.y), wp[13], c1);
    c0 = ffma2(splat2(A3.z), wp[14], c0);  c1 = ffma2(splat2(A3.w), wp[15], c1);
    return fadd2(c0, c1);
}

// TWO warps per node (2 cols/lane), persistent grid-stride over nodes.
// Pipelining is done via L2 prefetch of NEXT pair's xw+ea (zero reg cost);
// current loads then hit L2. Low regs -> 3 blocks/SM -> 24 warps for latency.
__global__ __launch_bounds__(256, 3)
void aggregate_kernel(const float* __restrict__ ea,
                      const float* __restrict__ ew,
                      const float* __restrict__ b,
                      float* __restrict__ out, int n) {
    int lane = threadIdx.x & 31;
    int gw = (blockIdx.x * blockDim.x + threadIdx.x) >> 5;
    int npairs = (gridDim.x * blockDim.x) >> 6;   // 2 warps per node-slot
    int pair = gw >> 1;
    int coff = (gw & 1) * 64 + lane * 2;          // this lane's 2 columns

    u64 pol_keep = policy_evict_last();
    u64 pol_stream = policy_evict_first();

    // Weight slice: ew[k][coff..coff+1] as one f32x2 each (32 regs). Once per warp.
    u64 wp[EDIM];
    #pragma unroll
    for (int k = 0; k < EDIM; k++)
        wp[k] = *(const u64*)&ew[k * DOUT + coff];
    u64 bias = *(const u64*)&b[coff];

    for (int v = pair; v < n; v += npairs) {
        int deg = g_cnt[v];
        if (deg > CAP) deg = CAP;

        u64 acc = bias;

        if (deg > 0) {
            const int2* bucket = &g_elist[(size_t)v * CAP];

            // Current pair (j=0,1); stale slot contents are valid ids, masked below.
            int4 se_c = *(const int4*)&bucket[0];
            if (deg < 2) { se_c.z = se_c.x; se_c.w = se_c.y; }
            // Warm L2 for pair 0.
            pf_l2(&g_xw[(size_t)se_c.x * DOUT + coff]);
            pf_l2(&g_xw[(size_t)se_c.z * DOUT + coff]);
            pf_l2(&ea[(size_t)se_c.y * EDIM]);
            pf_l2(&ea[(size_t)se_c.w * EDIM]);

            for (int j = 0; j < deg; j += 2) {
                // ---- prefetch pair j+2 to L2 (no registers held) ----
                int jn = (j + 2 < deg) ? (j + 2) : 0;
                int4 se_n = *(const int4*)&bucket[jn];
                if (j + 3 >= deg) { se_n.z = se_n.x; se_n.w = se_n.y; }
                pf_l2(&g_xw[(size_t)se_n.x * DOUT + coff]);
                pf_l2(&g_xw[(size_t)se_n.z * DOUT + coff]);
                pf_l2(&ea[(size_t)se_n.y * EDIM]);
                pf_l2(&ea[(size_t)se_n.w * EDIM]);

                // ---- issue all current loads up front (MLP) ----
                u64 xv0 = ldg_xw(&g_xw[(size_t)se_c.x * DOUT + coff], pol_keep);
                u64 xv1 = ldg_xw(&g_xw[(size_t)se_c.z * DOUT + coff], pol_keep);
                const float4* ep0 = (const float4*)&ea[(size_t)se_c.y * EDIM];
                float4 P0 = ldg_ea(&ep0[0], pol_stream);
                float4 P1 = ldg_ea(&ep0[1], pol_stream);
                float4 P2 = ldg_ea(&ep0[2], pol_stream);
                float4 P3 = ldg_ea(&ep0[3], pol_stream);

                bool v1 = (j + 1 < deg);
                const float4* ep1 = (const float4*)&ea[(size_t)se_c.w * EDIM];
                float4 Z = {0, 0, 0, 0};
                float4 Q0 = v1 ? ldg_ea(&ep1[0], pol_stream) : Z;
                float4 Q1 = v1 ? ldg_ea(&ep1[1], pol_stream) : Z;
                float4 Q2 = v1 ? ldg_ea(&ep1[2], pol_stream) : Z;
                float4 Q3 = v1 ? ldg_ea(&ep1[3], pol_stream) : Z;

                // ---- math ----
                u64 m0 = modulate2(P0, P1, P2, P3, wp);
                acc = ffma2(m0, xv0, acc);
                u64 m1 = modulate2(Q0, Q1, Q2, Q3, wp);  // 0 when !v1
                acc = ffma2(m1, xv1, acc);

                se_c = se_n;
            }
        }

        st_out(&out[(size_t)v * DOUT + coff], pol_stream, acc);
    }
}

extern "C" void kernel_launch(void* const* d_in, const int* in_sizes, int n_in,
                              void* d_out, int out_size) {
    const float* x  = (const float*)d_in[0];
    const int*   ei = (const int*)d_in[1];
    const float* ea = (const float*)d_in[2];
    const float* W  = (const float*)d_in[3];
    const float* ew = (const float*)d_in[4];
    const float* b  = (const float*)d_in[5];
    float* out = (float*)d_out;

    int n  = in_sizes[0] / DOUT;   // 100000 nodes
    int nE = in_sizes[1] / 2;      // 800000 edges

    zero_cnt_kernel<<<(n + 255) / 256, 256>>>(n);
    gemm_xw_kernel<<<(n + 63) / 64, 256>>>(x, W, n);
    scatter_kernel<<<(nE + 255) / 256, 256>>>(ei, nE);
    aggregate_kernel<<<444, 256>>>(ea, ew, b, out, n);   // 3552 warps = 1776 node-slots
}